// round 9
// baseline (speedup 1.0000x reference)
#include <cuda_runtime.h>
#include <math.h>

#define BB 8
#define DD 256
#define NL 10000
#define KN 32
#define KC 10032
#define NS 100

#define HISTB (NS * BB)            // 800 histogram CTAs
#define QPB   (KC / 4)             // 2508 quads per b
#define LOGB  (BB * QPB / 8)       // 2508 logits CTAs (8 quads each)
#define TOTB  (HISTB + LOGB)

// scratch (no allocations allowed)
__device__ float g_logits[BB * KC];            // for slow path only
__device__ float g_bootT[BB * DD * NS];        // [(b*DD+d)*NS + n]
__device__ int   g_cnt[NS * BB * 32];          // per-sample new-particle counts
__device__ unsigned g_MliveU[BB];              // encoded max live logit (0 = -inf; reset by k_final)

__device__ __forceinline__ unsigned fenc(float f) {
    unsigned u = __float_as_uint(f);
    return (u & 0x80000000u) ? ~u : (u | 0x80000000u);
}
__device__ __forceinline__ float fdec(unsigned u) {
    return (u & 0x80000000u) ? __uint_as_float(u & 0x7FFFFFFFu) : __uint_as_float(~u);
}

__device__ __forceinline__ float dsq(float4 a, float4 c) {
    float d0 = a.x - c.x, d1 = a.y - c.y, d2 = a.z - c.z, d3 = a.w - c.w;
    return d0 * d0 + d1 * d1 + d2 * d2 + d3 * d3;
}

__device__ __forceinline__ float blockMax256(float v, float* red) {
#pragma unroll
    for (int o = 16; o; o >>= 1) v = fmaxf(v, __shfl_xor_sync(0xffffffffu, v, o));
    int wid = threadIdx.x >> 5;
    if ((threadIdx.x & 31) == 0) red[wid] = v;
    __syncthreads();
    if (threadIdx.x < 32) {
        float x = (threadIdx.x < 8) ? red[threadIdx.x] : -INFINITY;
#pragma unroll
        for (int o = 4; o; o >>= 1) x = fmaxf(x, __shfl_xor_sync(0xffffffffu, x, o));
        if (threadIdx.x == 0) red[0] = x;
    }
    __syncthreads();
    v = red[0];
    __syncthreads();
    return v;
}

__device__ __forceinline__ float blockSum256(float v, float* red) {
#pragma unroll
    for (int o = 16; o; o >>= 1) v += __shfl_xor_sync(0xffffffffu, v, o);
    int wid = threadIdx.x >> 5;
    if ((threadIdx.x & 31) == 0) red[wid] = v;
    __syncthreads();
    if (threadIdx.x < 32) {
        float x = (threadIdx.x < 8) ? red[threadIdx.x] : 0.f;
#pragma unroll
        for (int o = 4; o; o >>= 1) x += __shfl_xor_sync(0xffffffffu, x, o);
        if (threadIdx.x == 0) red[0] = x;
    }
    __syncthreads();
    v = red[0];
    __syncthreads();
    return v;
}

// ---------- kernel 1: fused logits (+live max) + idx histogram ----------
// launch_bounds(256,2): reg cap 128 so all 8 row loads stay batched (MLP ~8)
__global__ void __launch_bounds__(256, 2)
k_fused(const float* __restrict__ xt,
        const float* __restrict__ live_x0,
        const float* __restrict__ live_ll,
        const float* __restrict__ ll,
        const float* __restrict__ tsp,
        const int* __restrict__ bidx) {
    __shared__ int cnt32[32];
    int bid = blockIdx.x, t = threadIdx.x;

    if (bid < HISTB) {
        // histogram of idx over the new-particle range [NL, KC)
        int n = bid >> 3, b = bid & 7;
        if (t < 32) cnt32[t] = 0;
        __syncthreads();
        const uint4* src = (const uint4*)(bidx + ((size_t)n * BB + b) * KC);
#pragma unroll 4
        for (int i = t; i < KC / 4; i += 256) {
            uint4 v = src[i];
            int s0 = (int)v.x - NL, s1 = (int)v.y - NL;
            int s2 = (int)v.z - NL, s3 = (int)v.w - NL;
            if (s0 >= 0) atomicAdd(&cnt32[s0], 1);
            if (s1 >= 0) atomicAdd(&cnt32[s1], 1);
            if (s2 >= 0) atomicAdd(&cnt32[s2], 1);
            if (s3 >= 0) atomicAdd(&cnt32[s3], 1);
        }
        __syncthreads();
        if (t < 32) g_cnt[((size_t)n * BB + b) * 32 + t] = cnt32[t];
        return;
    }

    // logits: 4 rows per warp, all loads batched before arithmetic
    int q = (bid - HISTB) * 8 + (t >> 5);
    int lane = t & 31;
    int b = q / QPB;
    int k0 = (q - b * QPB) * 4;
    if (k0 >= NL) {  // new particles: logits = ll exactly (cancellation)
        if (lane < 4) g_logits[(size_t)b * KC + k0 + lane] = ll[b * KN + (k0 - NL) + lane];
        return;
    }
    const float4* xtr = (const float4*)(xt + (size_t)b * DD);
    float4 c0 = xtr[lane], c1 = xtr[lane + 32];
    const float4* r0 = (const float4*)(live_x0 + ((size_t)b * NL + k0) * DD);
    const float4* r1 = r0 + (DD / 4);
    const float4* r2 = r1 + (DD / 4);
    const float4* r3 = r2 + (DD / 4);
    float4 a00 = r0[lane], a01 = r0[lane + 32];
    float4 a10 = r1[lane], a11 = r1[lane + 32];
    float4 a20 = r2[lane], a21 = r2[lane + 32];
    float4 a30 = r3[lane], a31 = r3[lane + 32];
    float s0 = dsq(a00, c0) + dsq(a01, c1);
    float s1 = dsq(a10, c0) + dsq(a11, c1);
    float s2 = dsq(a20, c0) + dsq(a21, c1);
    float s3 = dsq(a30, c0) + dsq(a31, c1);
#pragma unroll
    for (int o = 16; o; o >>= 1) {
        s0 += __shfl_xor_sync(0xffffffffu, s0, o);
        s1 += __shfl_xor_sync(0xffffffffu, s1, o);
        s2 += __shfl_xor_sync(0xffffffffu, s2, o);
        s3 += __shfl_xor_sync(0xffffffffu, s3, o);
    }
    if (lane == 0) {
        float ts = *tsp;
        float inv2 = 0.5f / (ts * ts), lg = logf(ts);
        size_t base = (size_t)b * KC + k0;
        const float* lr = live_ll + (size_t)b * NL + k0;
        float l0 = lr[0] - s0 * inv2 - lg;
        float l1 = lr[1] - s1 * inv2 - lg;
        float l2 = lr[2] - s2 * inv2 - lg;
        float l3 = lr[3] - s3 * inv2 - lg;
        g_logits[base] = l0; g_logits[base + 1] = l1;
        g_logits[base + 2] = l2; g_logits[base + 3] = l3;
        float lm = fmaxf(fmaxf(l0, l1), fmaxf(l2, l3));
        atomicMax(&g_MliveU[b], fenc(lm));
    }
}

// ---------- kernel 2: bootstrap + final score (grid = [NS+1, B]) ----------
__global__ void k_boot(const float* __restrict__ xt,
                       const float* __restrict__ live_x0,
                       const float* __restrict__ x0,
                       const float* __restrict__ ll,
                       const int* __restrict__ bidx,
                       const float* __restrict__ tsp,
                       float* __restrict__ out) {
    __shared__ float warr[32];
    __shared__ float shmz[2];
    __shared__ float red[8];
    int n = blockIdx.x, b = blockIdx.y, t = threadIdx.x;
    bool is_score = (n == NS);

    // warp 0: active weights from ll + counts (new particles only)
    if (t < 32) {
        int c = is_score ? 1 : g_cnt[((size_t)n * BB + b) * 32 + t];
        float lv = ll[b * KN + t];
        float lm = (c > 0) ? lv : -INFINITY;
        float m = lm;
#pragma unroll
        for (int o = 16; o; o >>= 1) m = fmaxf(m, __shfl_xor_sync(0xffffffffu, m, o));
        float w = (c > 0) ? (float)c * expf(lv - m) : 0.f;
        float z = w;
#pragma unroll
        for (int o = 16; o; o >>= 1) z += __shfl_xor_sync(0xffffffffu, z, o);
        warr[t] = w;
        if (t == 0) { shmz[0] = m; shmz[1] = z; }
    }
    __syncthreads();
    float m = shmz[0], z = shmz[1];
    float Mlive = fdec(g_MliveU[b]);
    float ts = *tsp;
    // all live weights underflow to exact 0 iff Mlive - m <= -90 (f32 expf cutoff ~ -104)
    bool fast = (m > -INFINITY) && (Mlive <= m - 90.f);

    float acc = 0.f;
    if (fast) {
        const float* xb = x0 + (size_t)b * KN * DD + t;
#pragma unroll
        for (int j = 0; j < KN; j += 4) {
            float v0 = xb[(j + 0) * DD];
            float v1 = xb[(j + 1) * DD];
            float v2 = xb[(j + 2) * DD];
            float v3 = xb[(j + 3) * DD];
            acc = fmaf(warr[j + 0], v0, acc);
            acc = fmaf(warr[j + 1], v1, acc);
            acc = fmaf(warr[j + 2], v2, acc);
            acc = fmaf(warr[j + 3], v3, acc);
        }
    } else {
        // exact slow path (never taken with this data)
        const int* idx = bidx + ((size_t)n * BB + b) * KC;
        const float* L = g_logits + (size_t)b * KC;
        float mm = -INFINITY;
        if (is_score) { for (int k = t; k < KC; k += 256) mm = fmaxf(mm, L[k]); }
        else          { for (int i = t; i < KC; i += 256) mm = fmaxf(mm, L[idx[i]]); }
        mm = blockMax256(mm, red);
        float zz = 0.f;
        if (is_score) { for (int k = t; k < KC; k += 256) zz += expf(L[k] - mm); }
        else          { for (int i = t; i < KC; i += 256) zz += expf(L[idx[i]] - mm); }
        z = blockSum256(zz, red);
        for (int i = 0; i < KC; i++) {
            int k = is_score ? i : idx[i];
            float w = expf(L[k] - mm);
            if (w != 0.f) {
                const float* r = (k < NL) ? live_x0 + ((size_t)b * NL + k) * DD
                                          : x0 + ((size_t)b * KN + (k - NL)) * DD;
                acc = fmaf(w, r[t], acc);
            }
        }
    }

    float val = acc / (z * ts) - xt[(size_t)b * DD + t] / ts;
    if (is_score) out[(size_t)b * DD + t] = val;
    else          g_bootT[((size_t)b * DD + t) * NS + n] = val;
}

// ---------- kernel 3: per-(b,d) std (ddof=1) + flags + replay reset ----------
__global__ void k_final(const float* __restrict__ tsp, float* __restrict__ out, int out_size) {
    int b = blockIdx.x, d = threadIdx.x;
    const float* p = g_bootT + ((size_t)b * DD + d) * NS;
    float x[NS];
    const float4* p4 = (const float4*)p;
#pragma unroll
    for (int i = 0; i < NS / 4; i++) {
        float4 v = p4[i];
        x[i * 4] = v.x; x[i * 4 + 1] = v.y; x[i * 4 + 2] = v.z; x[i * 4 + 3] = v.w;
    }
    float s = 0.f;
#pragma unroll
    for (int i = 0; i < NS; i++) s += x[i];
    float mean = s * (1.f / NS);
    float q = 0.f;
#pragma unroll
    for (int i = 0; i < NS; i++) { float dv = x[i] - mean; q = fmaf(dv, dv, q); }
    float sigma = sqrtf(q * (1.f / (NS - 1)));
    int ok = sigma < 0.1f * (*tsp);
    int all = __syncthreads_and(ok);
    if (d == 0) {
        if (out_size >= BB * DD + BB) out[BB * DD + b] = all ? 1.f : 0.f;
        g_MliveU[b] = 0u;  // reset for next graph replay
    }
}

extern "C" void kernel_launch(void* const* d_in, const int* in_sizes, int n_in,
                              void* d_out, int out_size) {
    const float* xt      = (const float*)d_in[0];
    const float* live_x0 = (const float*)d_in[1];
    const float* live_ll = (const float*)d_in[2];
    const float* x0      = (const float*)d_in[3];
    const float* ll      = (const float*)d_in[4];
    const float* tsp     = (const float*)d_in[5];
    const int*   bidx    = (const int*)d_in[6];
    float* out = (float*)d_out;

    k_fused<<<TOTB, 256>>>(xt, live_x0, live_ll, ll, tsp, bidx);

    dim3 g2(NS + 1, BB);
    k_boot<<<g2, 256>>>(xt, live_x0, x0, ll, bidx, tsp, out);

    k_final<<<BB, 256>>>(tsp, out, out_size);
}

// round 11
// speedup vs baseline: 1.7246x; 1.7246x over previous
#include <cuda_runtime.h>
#include <math.h>

#define BB 8
#define DD 256
#define NL 10000
#define KN 32
#define KC 10032
#define NS 100

#define HISTB (NS * BB)                 // 800 histogram CTAs
#define ROWS_PER_CTA 64
#define SCAN_PER_B ((NL + ROWS_PER_CTA - 1) / ROWS_PER_CTA)   // 157
#define SCANB (BB * SCAN_PER_B)         // 1256
#define TOTB (HISTB + SCANB + 1)        // +1 new-logit writer CTA
#define FLAG_THR (-100.0f)

// scratch (no allocations allowed)
__device__ float g_logits[BB * KC];            // UB for unflagged live, exact for flagged/new
__device__ float g_bootT[BB * DD * NS];        // [(b*DD+d)*NS + n]
__device__ int   g_cnt[NS * BB * 32];          // per-sample new-particle counts
__device__ unsigned g_MliveU[BB];              // encoded max flagged live logit (0 = none)
__device__ int   g_nwork[BB];                  // flagged-row counts (reset by k_final)
__device__ int   g_work[BB * NL];              // flagged row indices

__device__ __forceinline__ unsigned fenc(float f) {
    unsigned u = __float_as_uint(f);
    return (u & 0x80000000u) ? ~u : (u | 0x80000000u);
}
__device__ __forceinline__ float fdec(unsigned u) {
    return (u & 0x80000000u) ? __uint_as_float(u & 0x7FFFFFFFu) : __uint_as_float(~u);
}

__device__ __forceinline__ float dsq(float4 a, float4 c) {
    float d0 = a.x - c.x, d1 = a.y - c.y, d2 = a.z - c.z, d3 = a.w - c.w;
    return d0 * d0 + d1 * d1 + d2 * d2 + d3 * d3;
}

__device__ __forceinline__ float blockMax256(float v, float* red) {
#pragma unroll
    for (int o = 16; o; o >>= 1) v = fmaxf(v, __shfl_xor_sync(0xffffffffu, v, o));
    int wid = threadIdx.x >> 5;
    if ((threadIdx.x & 31) == 0) red[wid] = v;
    __syncthreads();
    if (threadIdx.x < 32) {
        float x = (threadIdx.x < 8) ? red[threadIdx.x] : -INFINITY;
#pragma unroll
        for (int o = 4; o; o >>= 1) x = fmaxf(x, __shfl_xor_sync(0xffffffffu, x, o));
        if (threadIdx.x == 0) red[0] = x;
    }
    __syncthreads();
    v = red[0];
    __syncthreads();
    return v;
}

__device__ __forceinline__ float blockSum256(float v, float* red) {
#pragma unroll
    for (int o = 16; o; o >>= 1) v += __shfl_xor_sync(0xffffffffu, v, o);
    int wid = threadIdx.x >> 5;
    if ((threadIdx.x & 31) == 0) red[wid] = v;
    __syncthreads();
    if (threadIdx.x < 32) {
        float x = (threadIdx.x < 8) ? red[threadIdx.x] : 0.f;
#pragma unroll
        for (int o = 4; o; o >>= 1) x += __shfl_xor_sync(0xffffffffu, x, o);
        if (threadIdx.x == 0) red[0] = x;
    }
    __syncthreads();
    v = red[0];
    __syncthreads();
    return v;
}

// ---------- kernel 1: fused idx histogram + 64-dim partial scan (upper bounds + worklist) ----------
__global__ void k_scan(const float* __restrict__ xt,
                       const float* __restrict__ live_x0,
                       const float* __restrict__ live_ll,
                       const float* __restrict__ ll,
                       const float* __restrict__ tsp,
                       const int* __restrict__ bidx) {
    __shared__ int cnt32[32];
    int bid = blockIdx.x, t = threadIdx.x;

    if (bid < HISTB) {
        // histogram of idx over the new-particle range [NL, KC)
        int n = bid >> 3, b = bid & 7;
        if (t < 32) cnt32[t] = 0;
        __syncthreads();
        const uint4* src = (const uint4*)(bidx + ((size_t)n * BB + b) * KC);
        for (int i = t; i < KC / 4; i += 256) {
            uint4 v = src[i];
            int s0 = (int)v.x - NL, s1 = (int)v.y - NL;
            int s2 = (int)v.z - NL, s3 = (int)v.w - NL;
            if (s0 >= 0) atomicAdd(&cnt32[s0], 1);
            if (s1 >= 0) atomicAdd(&cnt32[s1], 1);
            if (s2 >= 0) atomicAdd(&cnt32[s2], 1);
            if (s3 >= 0) atomicAdd(&cnt32[s3], 1);
        }
        __syncthreads();
        if (t < 32) g_cnt[((size_t)n * BB + b) * 32 + t] = cnt32[t];
        return;
    }
    if (bid == HISTB + SCANB) {
        // new-particle logits: exactly ll (gaussian correction cancels)
        int b = t >> 5, j = t & 31;
        g_logits[(size_t)b * KC + NL + j] = ll[b * KN + j];
        return;
    }

    // partial scan: first 64 dims of each live row -> upper bound on its logit.
    // 8 warps x (4 rows via 16-lane half-warps x 2) = 64 rows per CTA.
    int s = bid - HISTB;
    int b = s / SCAN_PER_B;
    int r0 = (s - b * SCAN_PER_B) * ROWS_PER_CTA;
    int w = t >> 5, lane = t & 31;
    int half = lane >> 4, sl = lane & 15;

    float ts = *tsp;
    float inv2 = 0.5f / (ts * ts), lg = logf(ts);
    const float4* xtr = (const float4*)(xt + (size_t)b * DD);
    float4 c = xtr[sl];  // first 64 floats of xt

    int rbase = r0 + w * 8 + half;  // rows rbase, rbase+2, rbase+4, rbase+6
    const float4* lx = (const float4*)(live_x0 + (size_t)b * NL * DD);

    int row0 = rbase, row1 = rbase + 2, row2 = rbase + 4, row3 = rbase + 6;
    bool v0 = row0 < NL, v1 = row1 < NL, v2 = row2 < NL, v3 = row3 < NL;
    float4 a0 = v0 ? lx[(size_t)row0 * (DD / 4) + sl] : c;
    float4 a1 = v1 ? lx[(size_t)row1 * (DD / 4) + sl] : c;
    float4 a2 = v2 ? lx[(size_t)row2 * (DD / 4) + sl] : c;
    float4 a3 = v3 ? lx[(size_t)row3 * (DD / 4) + sl] : c;
    float q0 = dsq(a0, c), q1 = dsq(a1, c), q2 = dsq(a2, c), q3 = dsq(a3, c);
#pragma unroll
    for (int o = 8; o; o >>= 1) {  // reduce within 16-lane half-warp
        q0 += __shfl_xor_sync(0xffffffffu, q0, o);
        q1 += __shfl_xor_sync(0xffffffffu, q1, o);
        q2 += __shfl_xor_sync(0xffffffffu, q2, o);
        q3 += __shfl_xor_sync(0xffffffffu, q3, o);
    }
    if (sl == 0) {
        const float* lr = live_ll + (size_t)b * NL;
        float* Lb = g_logits + (size_t)b * KC;
        float qs[4] = {q0, q1, q2, q3};
#pragma unroll
        for (int j = 0; j < 4; j++) {
            int row = rbase + 2 * j;
            if (row < NL) {
                float ub = lr[row] - qs[j] * inv2 - lg;   // upper bound (partial distance >= 0)
                Lb[row] = ub;
                if (ub > FLAG_THR) {
                    int pos = atomicAdd(&g_nwork[b], 1);
                    g_work[b * NL + pos] = row;
                }
            }
        }
    }
}

// ---------- kernel 2: exact logits for flagged rows (few; one warp per row slot) ----------
__global__ void k_exact(const float* __restrict__ xt,
                        const float* __restrict__ live_x0,
                        const float* __restrict__ live_ll,
                        const float* __restrict__ tsp) {
    int cta = blockIdx.x, t = threadIdx.x;
    int b = cta & 7;
    int wi = (cta >> 3) * 8 + (t >> 5);  // warp index within b: 0..63
    int lane = t & 31;
    int nw = g_nwork[b];
    float ts = *tsp;
    float inv2 = 0.5f / (ts * ts), lg = logf(ts);
    const float4* xtr = (const float4*)(xt + (size_t)b * DD);
    float4 c0 = xtr[lane], c1 = xtr[lane + 32];
    for (int i = wi; i < nw; i += 64) {
        int row = g_work[b * NL + i];
        const float4* r = (const float4*)(live_x0 + ((size_t)b * NL + row) * DD);
        float4 a0 = r[lane], a1 = r[lane + 32];
        float s = dsq(a0, c0) + dsq(a1, c1);
#pragma unroll
        for (int o = 16; o; o >>= 1) s += __shfl_xor_sync(0xffffffffu, s, o);
        if (lane == 0) {
            float l = live_ll[(size_t)b * NL + row] - s * inv2 - lg;
            g_logits[(size_t)b * KC + row] = l;
            atomicMax(&g_MliveU[b], fenc(l));
        }
    }
}

// ---------- kernel 3: bootstrap + final score (grid = [NS+1, B]) ----------
__global__ void k_boot(const float* __restrict__ xt,
                       const float* __restrict__ live_x0,
                       const float* __restrict__ x0,
                       const float* __restrict__ ll,
                       const int* __restrict__ bidx,
                       const float* __restrict__ tsp,
                       float* __restrict__ out) {
    __shared__ float warr[32];
    __shared__ float shmz[2];
    __shared__ float red[8];
    int n = blockIdx.x, b = blockIdx.y, t = threadIdx.x;
    bool is_score = (n == NS);

    if (t < 32) {
        int c = is_score ? 1 : g_cnt[((size_t)n * BB + b) * 32 + t];
        float lv = ll[b * KN + t];
        float lm = (c > 0) ? lv : -INFINITY;
        float m = lm;
#pragma unroll
        for (int o = 16; o; o >>= 1) m = fmaxf(m, __shfl_xor_sync(0xffffffffu, m, o));
        float w = (c > 0) ? (float)c * expf(lv - m) : 0.f;
        float z = w;
#pragma unroll
        for (int o = 16; o; o >>= 1) z += __shfl_xor_sync(0xffffffffu, z, o);
        warr[t] = w;
        if (t == 0) { shmz[0] = m; shmz[1] = z; }
    }
    __syncthreads();
    float m = shmz[0], z = shmz[1];
    unsigned mu = g_MliveU[b];
    float Mlive = mu ? fdec(mu) : -INFINITY;
    Mlive = fmaxf(Mlive, FLAG_THR);  // unflagged rows are <= FLAG_THR by construction
    float ts = *tsp;
    // all live weights underflow to exact 0 iff Mlive <= m - 90 (f32 expf cutoff ~ -104)
    bool fast = (m > -INFINITY) && (Mlive <= m - 90.f);

    float acc = 0.f;
    if (fast) {
        const float* xb = x0 + (size_t)b * KN * DD + t;
#pragma unroll
        for (int j = 0; j < KN; j += 4) {
            float v0 = xb[(j + 0) * DD];
            float v1 = xb[(j + 1) * DD];
            float v2 = xb[(j + 2) * DD];
            float v3 = xb[(j + 3) * DD];
            acc = fmaf(warr[j + 0], v0, acc);
            acc = fmaf(warr[j + 1], v1, acc);
            acc = fmaf(warr[j + 2], v2, acc);
            acc = fmaf(warr[j + 3], v3, acc);
        }
    } else {
        // exact slow path (never taken with this data; g_logits live entries are exact
        // for flagged rows and upper bounds whose weight is identically 0 otherwise)
        const int* idx = bidx + ((size_t)n * BB + b) * KC;
        const float* L = g_logits + (size_t)b * KC;
        float mm = -INFINITY;
        if (is_score) { for (int k = t; k < KC; k += 256) mm = fmaxf(mm, L[k]); }
        else          { for (int i = t; i < KC; i += 256) mm = fmaxf(mm, L[idx[i]]); }
        mm = blockMax256(mm, red);
        float zz = 0.f;
        if (is_score) { for (int k = t; k < KC; k += 256) zz += expf(L[k] - mm); }
        else          { for (int i = t; i < KC; i += 256) zz += expf(L[idx[i]] - mm); }
        z = blockSum256(zz, red);
        for (int i = 0; i < KC; i++) {
            int k = is_score ? i : idx[i];
            float w = expf(L[k] - mm);
            if (w != 0.f) {
                const float* r = (k < NL) ? live_x0 + ((size_t)b * NL + k) * DD
                                          : x0 + ((size_t)b * KN + (k - NL)) * DD;
                acc = fmaf(w, r[t], acc);
            }
        }
    }

    float val = acc / (z * ts) - xt[(size_t)b * DD + t] / ts;
    if (is_score) out[(size_t)b * DD + t] = val;
    else          g_bootT[((size_t)b * DD + t) * NS + n] = val;
}

// ---------- kernel 4: per-(b,d) std (ddof=1) + flags + replay reset ----------
__global__ void k_final(const float* __restrict__ tsp, float* __restrict__ out, int out_size) {
    int b = blockIdx.x, d = threadIdx.x;
    const float* p = g_bootT + ((size_t)b * DD + d) * NS;
    float x[NS];
    const float4* p4 = (const float4*)p;
#pragma unroll
    for (int i = 0; i < NS / 4; i++) {
        float4 v = p4[i];
        x[i * 4] = v.x; x[i * 4 + 1] = v.y; x[i * 4 + 2] = v.z; x[i * 4 + 3] = v.w;
    }
    float s = 0.f;
#pragma unroll
    for (int i = 0; i < NS; i++) s += x[i];
    float mean = s * (1.f / NS);
    float q = 0.f;
#pragma unroll
    for (int i = 0; i < NS; i++) { float dv = x[i] - mean; q = fmaf(dv, dv, q); }
    float sigma = sqrtf(q * (1.f / (NS - 1)));
    int ok = sigma < 0.1f * (*tsp);
    int all = __syncthreads_and(ok);
    if (d == 0) {
        if (out_size >= BB * DD + BB) out[BB * DD + b] = all ? 1.f : 0.f;
        g_MliveU[b] = 0u;   // reset for next graph replay
        g_nwork[b] = 0;
    }
}

extern "C" void kernel_launch(void* const* d_in, const int* in_sizes, int n_in,
                              void* d_out, int out_size) {
    const float* xt      = (const float*)d_in[0];
    const float* live_x0 = (const float*)d_in[1];
    const float* live_ll = (const float*)d_in[2];
    const float* x0      = (const float*)d_in[3];
    const float* ll      = (const float*)d_in[4];
    const float* tsp     = (const float*)d_in[5];
    const int*   bidx    = (const int*)d_in[6];
    float* out = (float*)d_out;

    k_scan<<<TOTB, 256>>>(xt, live_x0, live_ll, ll, tsp, bidx);
    k_exact<<<64, 256>>>(xt, live_x0, live_ll, tsp);

    dim3 g2(NS + 1, BB);
    k_boot<<<g2, 256>>>(xt, live_x0, x0, ll, bidx, tsp, out);

    k_final<<<BB, 256>>>(tsp, out, out_size);
}

// round 13
// speedup vs baseline: 1.8675x; 1.0828x over previous
#include <cuda_runtime.h>
#include <math.h>

#define BB 8
#define DD 256
#define NL 10000
#define KN 32
#define KC 10032
#define NS 100

#define HISTB (NS * BB)                 // 800 histogram CTAs
#define ROWS_PER_CTA 64
#define SCAN_PER_B ((NL + ROWS_PER_CTA - 1) / ROWS_PER_CTA)   // 157
#define SCANB (BB * SCAN_PER_B)         // 1256
#define TOTB (HISTB + SCANB + 1)        // +1 new-logit writer CTA
#define FLAG_THR (-100.0f)

// scratch (no allocations allowed)
__device__ float g_logits[BB * KC];            // UB for unflagged live, exact for flagged/new
__device__ float g_boot[NS * BB * DD];         // [n][b*DD+d]  (coalesced both sides)
__device__ int   g_cnt[NS * BB * 32];          // per-sample new-particle counts
__device__ unsigned g_MliveU[BB];              // encoded max flagged live logit (0 = none)
__device__ int   g_nwork[BB];                  // flagged-row counts (reset by k_final)
__device__ int   g_work[BB * NL];              // flagged row indices

__device__ __forceinline__ unsigned fenc(float f) {
    unsigned u = __float_as_uint(f);
    return (u & 0x80000000u) ? ~u : (u | 0x80000000u);
}
__device__ __forceinline__ float fdec(unsigned u) {
    return (u & 0x80000000u) ? __uint_as_float(u & 0x7FFFFFFFu) : __uint_as_float(~u);
}

__device__ __forceinline__ float dsq(float4 a, float4 c) {
    float d0 = a.x - c.x, d1 = a.y - c.y, d2 = a.z - c.z, d3 = a.w - c.w;
    return d0 * d0 + d1 * d1 + d2 * d2 + d3 * d3;
}

__device__ __forceinline__ float blockMax256(float v, float* red) {
#pragma unroll
    for (int o = 16; o; o >>= 1) v = fmaxf(v, __shfl_xor_sync(0xffffffffu, v, o));
    int wid = threadIdx.x >> 5;
    if ((threadIdx.x & 31) == 0) red[wid] = v;
    __syncthreads();
    if (threadIdx.x < 32) {
        float x = (threadIdx.x < 8) ? red[threadIdx.x] : -INFINITY;
#pragma unroll
        for (int o = 4; o; o >>= 1) x = fmaxf(x, __shfl_xor_sync(0xffffffffu, x, o));
        if (threadIdx.x == 0) red[0] = x;
    }
    __syncthreads();
    v = red[0];
    __syncthreads();
    return v;
}

__device__ __forceinline__ float blockSum256(float v, float* red) {
#pragma unroll
    for (int o = 16; o; o >>= 1) v += __shfl_xor_sync(0xffffffffu, v, o);
    int wid = threadIdx.x >> 5;
    if ((threadIdx.x & 31) == 0) red[wid] = v;
    __syncthreads();
    if (threadIdx.x < 32) {
        float x = (threadIdx.x < 8) ? red[threadIdx.x] : 0.f;
#pragma unroll
        for (int o = 4; o; o >>= 1) x += __shfl_xor_sync(0xffffffffu, x, o);
        if (threadIdx.x == 0) red[0] = x;
    }
    __syncthreads();
    v = red[0];
    __syncthreads();
    return v;
}

// ---------- kernel 1: fused idx histogram + 64-dim partial scan (upper bounds + worklist) ----------
__global__ void k_scan(const float* __restrict__ xt,
                       const float* __restrict__ live_x0,
                       const float* __restrict__ live_ll,
                       const float* __restrict__ ll,
                       const float* __restrict__ tsp,
                       const int* __restrict__ bidx) {
    __shared__ int cnt32[32];
    int bid = blockIdx.x, t = threadIdx.x;

    if (bid < HISTB) {
        // histogram of idx over the new-particle range [NL, KC)
        int n = bid >> 3, b = bid & 7;
        if (t < 32) cnt32[t] = 0;
        __syncthreads();
        const uint4* src = (const uint4*)(bidx + ((size_t)n * BB + b) * KC);
        for (int i = t; i < KC / 4; i += 256) {
            uint4 v = src[i];
            int s0 = (int)v.x - NL, s1 = (int)v.y - NL;
            int s2 = (int)v.z - NL, s3 = (int)v.w - NL;
            if (s0 >= 0) atomicAdd(&cnt32[s0], 1);
            if (s1 >= 0) atomicAdd(&cnt32[s1], 1);
            if (s2 >= 0) atomicAdd(&cnt32[s2], 1);
            if (s3 >= 0) atomicAdd(&cnt32[s3], 1);
        }
        __syncthreads();
        if (t < 32) g_cnt[((size_t)n * BB + b) * 32 + t] = cnt32[t];
        return;
    }
    if (bid == HISTB + SCANB) {
        // new-particle logits: exactly ll (gaussian correction cancels)
        int b = t >> 5, j = t & 31;
        g_logits[(size_t)b * KC + NL + j] = ll[b * KN + j];
        return;
    }

    // partial scan: first 64 dims of each live row -> upper bound on its logit.
    int s = bid - HISTB;
    int b = s / SCAN_PER_B;
    int r0 = (s - b * SCAN_PER_B) * ROWS_PER_CTA;
    int w = t >> 5, lane = t & 31;
    int half = lane >> 4, sl = lane & 15;

    float ts = *tsp;
    float inv2 = 0.5f / (ts * ts), lg = logf(ts);
    const float4* xtr = (const float4*)(xt + (size_t)b * DD);
    float4 c = xtr[sl];  // first 64 floats of xt

    int rbase = r0 + w * 8 + half;  // rows rbase, rbase+2, rbase+4, rbase+6
    const float4* lx = (const float4*)(live_x0 + (size_t)b * NL * DD);

    int row0 = rbase, row1 = rbase + 2, row2 = rbase + 4, row3 = rbase + 6;
    bool v0 = row0 < NL, v1 = row1 < NL, v2 = row2 < NL, v3 = row3 < NL;
    float4 a0 = v0 ? lx[(size_t)row0 * (DD / 4) + sl] : c;
    float4 a1 = v1 ? lx[(size_t)row1 * (DD / 4) + sl] : c;
    float4 a2 = v2 ? lx[(size_t)row2 * (DD / 4) + sl] : c;
    float4 a3 = v3 ? lx[(size_t)row3 * (DD / 4) + sl] : c;
    float q0 = dsq(a0, c), q1 = dsq(a1, c), q2 = dsq(a2, c), q3 = dsq(a3, c);
#pragma unroll
    for (int o = 8; o; o >>= 1) {  // reduce within 16-lane half-warp
        q0 += __shfl_xor_sync(0xffffffffu, q0, o);
        q1 += __shfl_xor_sync(0xffffffffu, q1, o);
        q2 += __shfl_xor_sync(0xffffffffu, q2, o);
        q3 += __shfl_xor_sync(0xffffffffu, q3, o);
    }
    if (sl == 0) {
        const float* lr = live_ll + (size_t)b * NL;
        float* Lb = g_logits + (size_t)b * KC;
        float qs[4] = {q0, q1, q2, q3};
#pragma unroll
        for (int j = 0; j < 4; j++) {
            int row = rbase + 2 * j;
            if (row < NL) {
                float ub = lr[row] - qs[j] * inv2 - lg;   // upper bound (partial distance >= 0)
                Lb[row] = ub;
                if (ub > FLAG_THR) {
                    int pos = atomicAdd(&g_nwork[b], 1);
                    g_work[b * NL + pos] = row;
                }
            }
        }
    }
}

// ---------- kernel 2: exact logits for flagged rows (one CTA per b, warp per row) ----------
__global__ void k_exact(const float* __restrict__ xt,
                        const float* __restrict__ live_x0,
                        const float* __restrict__ live_ll,
                        const float* __restrict__ tsp) {
    int b = blockIdx.x, t = threadIdx.x;
    int wi = t >> 5, lane = t & 31;
    int nw = g_nwork[b];
    float ts = *tsp;
    float inv2 = 0.5f / (ts * ts), lg = logf(ts);
    const float4* xtr = (const float4*)(xt + (size_t)b * DD);
    float4 c0 = xtr[lane], c1 = xtr[lane + 32];
    for (int i = wi; i < nw; i += 8) {
        int row = g_work[b * NL + i];
        const float4* r = (const float4*)(live_x0 + ((size_t)b * NL + row) * DD);
        float4 a0 = r[lane], a1 = r[lane + 32];
        float s = dsq(a0, c0) + dsq(a1, c1);
#pragma unroll
        for (int o = 16; o; o >>= 1) s += __shfl_xor_sync(0xffffffffu, s, o);
        if (lane == 0) {
            float l = live_ll[(size_t)b * NL + row] - s * inv2 - lg;
            g_logits[(size_t)b * KC + row] = l;
            atomicMax(&g_MliveU[b], fenc(l));
        }
    }
}

// ---------- kernel 3: bootstrap + final score (grid = [NS+1, B]) ----------
__global__ void k_boot(const float* __restrict__ xt,
                       const float* __restrict__ live_x0,
                       const float* __restrict__ x0,
                       const float* __restrict__ ll,
                       const int* __restrict__ bidx,
                       const float* __restrict__ tsp,
                       float* __restrict__ out) {
    __shared__ float warr[32];
    __shared__ float shmz[2];
    __shared__ float red[8];
    int n = blockIdx.x, b = blockIdx.y, t = threadIdx.x;
    bool is_score = (n == NS);

    if (t < 32) {
        int c = is_score ? 1 : g_cnt[((size_t)n * BB + b) * 32 + t];
        float lv = ll[b * KN + t];
        float lm = (c > 0) ? lv : -INFINITY;
        float m = lm;
#pragma unroll
        for (int o = 16; o; o >>= 1) m = fmaxf(m, __shfl_xor_sync(0xffffffffu, m, o));
        float w = (c > 0) ? (float)c * expf(lv - m) : 0.f;
        float z = w;
#pragma unroll
        for (int o = 16; o; o >>= 1) z += __shfl_xor_sync(0xffffffffu, z, o);
        warr[t] = w;
        if (t == 0) { shmz[0] = m; shmz[1] = z; }
    }
    __syncthreads();
    float m = shmz[0], z = shmz[1];
    unsigned mu = g_MliveU[b];
    float Mlive = mu ? fdec(mu) : -INFINITY;
    Mlive = fmaxf(Mlive, FLAG_THR);  // unflagged rows are <= FLAG_THR by construction
    float ts = *tsp;
    // all live weights underflow to exact 0 iff Mlive <= m - 90 (f32 expf cutoff ~ -104)
    bool fast = (m > -INFINITY) && (Mlive <= m - 90.f);

    float acc = 0.f;
    if (fast) {
        const float* xb = x0 + (size_t)b * KN * DD + t;
#pragma unroll
        for (int j = 0; j < KN; j += 4) {
            float v0 = xb[(j + 0) * DD];
            float v1 = xb[(j + 1) * DD];
            float v2 = xb[(j + 2) * DD];
            float v3 = xb[(j + 3) * DD];
            acc = fmaf(warr[j + 0], v0, acc);
            acc = fmaf(warr[j + 1], v1, acc);
            acc = fmaf(warr[j + 2], v2, acc);
            acc = fmaf(warr[j + 3], v3, acc);
        }
    } else {
        // exact slow path (never taken with this data; g_logits live entries are exact
        // for flagged rows and upper bounds whose weight is identically 0 otherwise)
        const int* idx = bidx + ((size_t)n * BB + b) * KC;
        const float* L = g_logits + (size_t)b * KC;
        float mm = -INFINITY;
        if (is_score) { for (int k = t; k < KC; k += 256) mm = fmaxf(mm, L[k]); }
        else          { for (int i = t; i < KC; i += 256) mm = fmaxf(mm, L[idx[i]]); }
        mm = blockMax256(mm, red);
        float zz = 0.f;
        if (is_score) { for (int k = t; k < KC; k += 256) zz += expf(L[k] - mm); }
        else          { for (int i = t; i < KC; i += 256) zz += expf(L[idx[i]] - mm); }
        z = blockSum256(zz, red);
        for (int i = 0; i < KC; i++) {
            int k = is_score ? i : idx[i];
            float w = expf(L[k] - mm);
            if (w != 0.f) {
                const float* r = (k < NL) ? live_x0 + ((size_t)b * NL + k) * DD
                                          : x0 + ((size_t)b * KN + (k - NL)) * DD;
                acc = fmaf(w, r[t], acc);
            }
        }
    }

    float val = acc / (z * ts) - xt[(size_t)b * DD + t] / ts;
    if (is_score) out[(size_t)b * DD + t] = val;
    else          g_boot[(size_t)n * (BB * DD) + b * DD + t] = val;  // coalesced
}

// ---------- kernel 4: per-(b,d) std (ddof=1) + flags + replay reset ----------
// CTA per b; thread d reads g_boot[n][b*DD+d]: warp reads 128B contiguous per n.
__global__ void k_final(const float* __restrict__ tsp, float* __restrict__ out, int out_size) {
    int b = blockIdx.x, d = threadIdx.x;
    const float* p = g_boot + (size_t)b * DD + d;
    float x[NS];
#pragma unroll
    for (int i = 0; i < NS; i++) x[i] = p[(size_t)i * (BB * DD)];
    float s = 0.f;
#pragma unroll
    for (int i = 0; i < NS; i++) s += x[i];
    float mean = s * (1.f / NS);
    float q = 0.f;
#pragma unroll
    for (int i = 0; i < NS; i++) { float dv = x[i] - mean; q = fmaf(dv, dv, q); }
    float sigma = sqrtf(q * (1.f / (NS - 1)));
    int ok = sigma < 0.1f * (*tsp);
    int all = __syncthreads_and(ok);
    if (d == 0) {
        if (out_size >= BB * DD + BB) out[BB * DD + b] = all ? 1.f : 0.f;
        g_MliveU[b] = 0u;   // reset for next graph replay
        g_nwork[b] = 0;
    }
}

extern "C" void kernel_launch(void* const* d_in, const int* in_sizes, int n_in,
                              void* d_out, int out_size) {
    const float* xt      = (const float*)d_in[0];
    const float* live_x0 = (const float*)d_in[1];
    const float* live_ll = (const float*)d_in[2];
    const float* x0      = (const float*)d_in[3];
    const float* ll      = (const float*)d_in[4];
    const float* tsp     = (const float*)d_in[5];
    const int*   bidx    = (const int*)d_in[6];
    float* out = (float*)d_out;

    k_scan<<<TOTB, 256>>>(xt, live_x0, live_ll, ll, tsp, bidx);
    k_exact<<<BB, 256>>>(xt, live_x0, live_ll, tsp);

    dim3 g2(NS + 1, BB);
    k_boot<<<g2, 256>>>(xt, live_x0, x0, ll, bidx, tsp, out);

    k_final<<<BB, 256>>>(tsp, out, out_size);
}

// round 14
// speedup vs baseline: 2.0736x; 1.1104x over previous
#include <cuda_runtime.h>
#include <math.h>

#define BB 8
#define DD 256
#define NL 10000
#define KN 32
#define KC 10032
#define NS 100

#define HISTB (NS * BB)                 // 800 histogram CTAs
#define ROWS_PER_CTA 64
#define SCAN_PER_B ((NL + ROWS_PER_CTA - 1) / ROWS_PER_CTA)   // 157
#define SCANB (BB * SCAN_PER_B)         // 1256
#define TOTB (HISTB + SCANB + 1)        // +1 new-logit/init writer CTA
#define FLAG_THR (-100.0f)

// scratch (no allocations allowed)
__device__ float g_logits[BB * KC];            // UB for unflagged live, exact for flagged/new
__device__ float g_boot[NS * BB * DD];         // [n][b*DD+d]  (coalesced both sides)
__device__ int   g_cnt[NS * BB * 32];          // per-sample new-particle counts
__device__ unsigned g_MliveU[BB];              // encoded max flagged live logit (0 = none; reset by k_final)
__device__ int   g_flag[BB];                   // converged flags (init by k_scan writer CTA)
__device__ int   g_tick = 0;                   // k_final ticket (reset by last CTA)

__device__ __forceinline__ unsigned fenc(float f) {
    unsigned u = __float_as_uint(f);
    return (u & 0x80000000u) ? ~u : (u | 0x80000000u);
}
__device__ __forceinline__ float fdec(unsigned u) {
    return (u & 0x80000000u) ? __uint_as_float(u & 0x7FFFFFFFu) : __uint_as_float(~u);
}

__device__ __forceinline__ float dsq(float4 a, float4 c) {
    float d0 = a.x - c.x, d1 = a.y - c.y, d2 = a.z - c.z, d3 = a.w - c.w;
    return d0 * d0 + d1 * d1 + d2 * d2 + d3 * d3;
}

__device__ __forceinline__ float blockMax256(float v, float* red) {
#pragma unroll
    for (int o = 16; o; o >>= 1) v = fmaxf(v, __shfl_xor_sync(0xffffffffu, v, o));
    int wid = threadIdx.x >> 5;
    if ((threadIdx.x & 31) == 0) red[wid] = v;
    __syncthreads();
    if (threadIdx.x < 32) {
        float x = (threadIdx.x < 8) ? red[threadIdx.x] : -INFINITY;
#pragma unroll
        for (int o = 4; o; o >>= 1) x = fmaxf(x, __shfl_xor_sync(0xffffffffu, x, o));
        if (threadIdx.x == 0) red[0] = x;
    }
    __syncthreads();
    v = red[0];
    __syncthreads();
    return v;
}

__device__ __forceinline__ float blockSum256(float v, float* red) {
#pragma unroll
    for (int o = 16; o; o >>= 1) v += __shfl_xor_sync(0xffffffffu, v, o);
    int wid = threadIdx.x >> 5;
    if ((threadIdx.x & 31) == 0) red[wid] = v;
    __syncthreads();
    if (threadIdx.x < 32) {
        float x = (threadIdx.x < 8) ? red[threadIdx.x] : 0.f;
#pragma unroll
        for (int o = 4; o; o >>= 1) x += __shfl_xor_sync(0xffffffffu, x, o);
        if (threadIdx.x == 0) red[0] = x;
    }
    __syncthreads();
    v = red[0];
    __syncthreads();
    return v;
}

// ---------- kernel 1: idx histogram + partial scan + inline exact resolve ----------
__global__ void k_scan(const float* __restrict__ xt,
                       const float* __restrict__ live_x0,
                       const float* __restrict__ live_ll,
                       const float* __restrict__ ll,
                       const float* __restrict__ tsp,
                       const int* __restrict__ bidx) {
    __shared__ int cnt32[32];
    __shared__ int fl_rows[ROWS_PER_CTA];
    __shared__ int fl_n;
    int bid = blockIdx.x, t = threadIdx.x;

    if (bid < HISTB) {
        // histogram of idx over the new-particle range [NL, KC)
        int n = bid >> 3, b = bid & 7;
        if (t < 32) cnt32[t] = 0;
        __syncthreads();
        const uint4* src = (const uint4*)(bidx + ((size_t)n * BB + b) * KC);
        for (int i = t; i < KC / 4; i += 256) {
            uint4 v = src[i];
            int s0 = (int)v.x - NL, s1 = (int)v.y - NL;
            int s2 = (int)v.z - NL, s3 = (int)v.w - NL;
            if (s0 >= 0) atomicAdd(&cnt32[s0], 1);
            if (s1 >= 0) atomicAdd(&cnt32[s1], 1);
            if (s2 >= 0) atomicAdd(&cnt32[s2], 1);
            if (s3 >= 0) atomicAdd(&cnt32[s3], 1);
        }
        __syncthreads();
        if (t < 32) g_cnt[((size_t)n * BB + b) * 32 + t] = cnt32[t];
        return;
    }
    if (bid == HISTB + SCANB) {
        // new-particle logits: exactly ll (gaussian correction cancels); init flags
        int b = t >> 5, j = t & 31;
        g_logits[(size_t)b * KC + NL + j] = ll[b * KN + j];
        if (t < BB) g_flag[t] = 1;
        return;
    }

    // partial scan: first 64 dims of each live row -> upper bound on its logit.
    int s = bid - HISTB;
    int b = s / SCAN_PER_B;
    int r0 = (s - b * SCAN_PER_B) * ROWS_PER_CTA;
    int w = t >> 5, lane = t & 31;
    int half = lane >> 4, sl = lane & 15;

    if (t == 0) fl_n = 0;
    __syncthreads();

    float ts = *tsp;
    float inv2 = 0.5f / (ts * ts), lg = logf(ts);
    const float4* xtr = (const float4*)(xt + (size_t)b * DD);
    float4 c = xtr[sl];  // first 64 floats of xt

    int rbase = r0 + w * 8 + half;  // rows rbase, rbase+2, rbase+4, rbase+6
    const float4* lx = (const float4*)(live_x0 + (size_t)b * NL * DD);

    int row0 = rbase, row1 = rbase + 2, row2 = rbase + 4, row3 = rbase + 6;
    bool v0 = row0 < NL, v1 = row1 < NL, v2 = row2 < NL, v3 = row3 < NL;
    float4 a0 = v0 ? lx[(size_t)row0 * (DD / 4) + sl] : c;
    float4 a1 = v1 ? lx[(size_t)row1 * (DD / 4) + sl] : c;
    float4 a2 = v2 ? lx[(size_t)row2 * (DD / 4) + sl] : c;
    float4 a3 = v3 ? lx[(size_t)row3 * (DD / 4) + sl] : c;
    float q0 = dsq(a0, c), q1 = dsq(a1, c), q2 = dsq(a2, c), q3 = dsq(a3, c);
#pragma unroll
    for (int o = 8; o; o >>= 1) {  // reduce within 16-lane half-warp
        q0 += __shfl_xor_sync(0xffffffffu, q0, o);
        q1 += __shfl_xor_sync(0xffffffffu, q1, o);
        q2 += __shfl_xor_sync(0xffffffffu, q2, o);
        q3 += __shfl_xor_sync(0xffffffffu, q3, o);
    }
    if (sl == 0) {
        const float* lr = live_ll + (size_t)b * NL;
        float* Lb = g_logits + (size_t)b * KC;
        float qs[4] = {q0, q1, q2, q3};
#pragma unroll
        for (int j = 0; j < 4; j++) {
            int row = rbase + 2 * j;
            if (row < NL) {
                float ub = lr[row] - qs[j] * inv2 - lg;   // upper bound (partial distance >= 0)
                Lb[row] = ub;
                if (ub > FLAG_THR) {
                    int pos = atomicAdd(&fl_n, 1);
                    fl_rows[pos] = row;   // <= 64 rows per CTA by construction
                }
            }
        }
    }
    __syncthreads();

    // inline exact resolve for flagged rows (rare): full 256-dim distance, warp per row
    int nf = fl_n;
    if (nf > 0) {
        float4 c0 = xtr[lane], c1 = xtr[lane + 32];
        for (int i = w; i < nf; i += 8) {
            int row = fl_rows[i];
            const float4* r = (const float4*)(live_x0 + ((size_t)b * NL + row) * DD);
            float4 e0 = r[lane], e1 = r[lane + 32];
            float sfull = dsq(e0, c0) + dsq(e1, c1);
#pragma unroll
            for (int o = 16; o; o >>= 1) sfull += __shfl_xor_sync(0xffffffffu, sfull, o);
            if (lane == 0) {
                float l = live_ll[(size_t)b * NL + row] - sfull * inv2 - lg;
                g_logits[(size_t)b * KC + row] = l;   // overwrite UB with exact
                atomicMax(&g_MliveU[b], fenc(l));
            }
        }
    }
}

// ---------- kernel 2: bootstrap + final score (grid = [NS+1, B]) ----------
__global__ void k_boot(const float* __restrict__ xt,
                       const float* __restrict__ live_x0,
                       const float* __restrict__ x0,
                       const float* __restrict__ ll,
                       const int* __restrict__ bidx,
                       const float* __restrict__ tsp,
                       float* __restrict__ out) {
    __shared__ float warr[32];
    __shared__ float shmz[2];
    __shared__ float red[8];
    int n = blockIdx.x, b = blockIdx.y, t = threadIdx.x;
    bool is_score = (n == NS);

    if (t < 32) {
        int c = is_score ? 1 : g_cnt[((size_t)n * BB + b) * 32 + t];
        float lv = ll[b * KN + t];
        float lm = (c > 0) ? lv : -INFINITY;
        float m = lm;
#pragma unroll
        for (int o = 16; o; o >>= 1) m = fmaxf(m, __shfl_xor_sync(0xffffffffu, m, o));
        float w = (c > 0) ? (float)c * expf(lv - m) : 0.f;
        float z = w;
#pragma unroll
        for (int o = 16; o; o >>= 1) z += __shfl_xor_sync(0xffffffffu, z, o);
        warr[t] = w;
        if (t == 0) { shmz[0] = m; shmz[1] = z; }
    }
    __syncthreads();
    float m = shmz[0], z = shmz[1];
    unsigned mu = g_MliveU[b];
    float Mlive = mu ? fdec(mu) : -INFINITY;
    Mlive = fmaxf(Mlive, FLAG_THR);  // unflagged rows are <= FLAG_THR by construction
    float ts = *tsp;
    // all live weights underflow to exact 0 iff Mlive <= m - 90 (f32 expf cutoff ~ -104)
    bool fast = (m > -INFINITY) && (Mlive <= m - 90.f);

    float acc = 0.f;
    if (fast) {
        const float* xb = x0 + (size_t)b * KN * DD + t;
#pragma unroll
        for (int j = 0; j < KN; j += 4) {
            float v0 = xb[(j + 0) * DD];
            float v1 = xb[(j + 1) * DD];
            float v2 = xb[(j + 2) * DD];
            float v3 = xb[(j + 3) * DD];
            acc = fmaf(warr[j + 0], v0, acc);
            acc = fmaf(warr[j + 1], v1, acc);
            acc = fmaf(warr[j + 2], v2, acc);
            acc = fmaf(warr[j + 3], v3, acc);
        }
    } else {
        // exact slow path (never taken with this data; g_logits live entries are exact
        // for flagged rows and upper bounds whose weight is identically 0 otherwise)
        const int* idx = bidx + ((size_t)n * BB + b) * KC;
        const float* L = g_logits + (size_t)b * KC;
        float mm = -INFINITY;
        if (is_score) { for (int k = t; k < KC; k += 256) mm = fmaxf(mm, L[k]); }
        else          { for (int i = t; i < KC; i += 256) mm = fmaxf(mm, L[idx[i]]); }
        mm = blockMax256(mm, red);
        float zz = 0.f;
        if (is_score) { for (int k = t; k < KC; k += 256) zz += expf(L[k] - mm); }
        else          { for (int i = t; i < KC; i += 256) zz += expf(L[idx[i]] - mm); }
        z = blockSum256(zz, red);
        for (int i = 0; i < KC; i++) {
            int k = is_score ? i : idx[i];
            float w = expf(L[k] - mm);
            if (w != 0.f) {
                const float* r = (k < NL) ? live_x0 + ((size_t)b * NL + k) * DD
                                          : x0 + ((size_t)b * KN + (k - NL)) * DD;
                acc = fmaf(w, r[t], acc);
            }
        }
    }

    float val = acc / (z * ts) - xt[(size_t)b * DD + t] / ts;
    if (is_score) out[(size_t)b * DD + t] = val;
    else          g_boot[(size_t)n * (BB * DD) + b * DD + t] = val;  // coalesced
}

// ---------- kernel 3: std (ddof=1) + flags, 32 CTAs (4 per b) ----------
// CTA (b, dg): 256 threads = 64 d-cols x 4 sample-groups of 25.
__global__ void k_final(const float* __restrict__ tsp, float* __restrict__ out, int out_size) {
    __shared__ float sred[4][64];
    __shared__ int tick;
    int cta = blockIdx.x;
    int b = cta >> 2, dg = cta & 3;
    int dj = threadIdx.x & 63, ng = threadIdx.x >> 6;
    int d = dg * 64 + dj;
    const float* p = g_boot + (size_t)b * DD + d + (size_t)(ng * 25) * (BB * DD);

    float x[25];
#pragma unroll
    for (int i = 0; i < 25; i++) x[i] = p[(size_t)i * (BB * DD)];
    float s = 0.f;
#pragma unroll
    for (int i = 0; i < 25; i++) s += x[i];
    sred[ng][dj] = s;
    __syncthreads();
    float mean = (sred[0][dj] + sred[1][dj] + sred[2][dj] + sred[3][dj]) * (1.f / NS);
    __syncthreads();
    float q = 0.f;
#pragma unroll
    for (int i = 0; i < 25; i++) { float dv = x[i] - mean; q = fmaf(dv, dv, q); }
    sred[ng][dj] = q;
    __syncthreads();

    int ok = 1;
    if (ng == 0) {
        float qt = sred[0][dj] + sred[1][dj] + sred[2][dj] + sred[3][dj];
        float sigma = sqrtf(qt * (1.f / (NS - 1)));
        ok = sigma < 0.1f * (*tsp);
    }
    int all = __syncthreads_and(ok);
    if (threadIdx.x == 0 && !all) atomicAnd(&g_flag[b], 0);
    __threadfence();
    __syncthreads();
    if (threadIdx.x == 0) tick = atomicAdd(&g_tick, 1);
    __syncthreads();
    if (tick == 31) {  // last CTA: emit flags + reset replay state
        if (threadIdx.x < BB) {
            if (out_size >= BB * DD + BB)
                out[BB * DD + threadIdx.x] = g_flag[threadIdx.x] ? 1.f : 0.f;
            g_MliveU[threadIdx.x] = 0u;
        }
        if (threadIdx.x == 0) g_tick = 0;
    }
}

extern "C" void kernel_launch(void* const* d_in, const int* in_sizes, int n_in,
                              void* d_out, int out_size) {
    const float* xt      = (const float*)d_in[0];
    const float* live_x0 = (const float*)d_in[1];
    const float* live_ll = (const float*)d_in[2];
    const float* x0      = (const float*)d_in[3];
    const float* ll      = (const float*)d_in[4];
    const float* tsp     = (const float*)d_in[5];
    const int*   bidx    = (const int*)d_in[6];
    float* out = (float*)d_out;

    k_scan<<<TOTB, 256>>>(xt, live_x0, live_ll, ll, tsp, bidx);

    dim3 g2(NS + 1, BB);
    k_boot<<<g2, 256>>>(xt, live_x0, x0, ll, bidx, tsp, out);

    k_final<<<32, 256>>>(tsp, out, out_size);
}

// round 15
// speedup vs baseline: 2.0946x; 1.0101x over previous
#include <cuda_runtime.h>
#include <math.h>

#define BB 8
#define DD 256
#define NL 10000
#define KN 32
#define KC 10032
#define NS 100

#define HISTB (NS * BB)                 // 800 histogram CTAs
#define ROWS_PER_CTA 64
#define SCAN_PER_B ((NL + ROWS_PER_CTA - 1) / ROWS_PER_CTA)   // 157
#define SCANB (BB * SCAN_PER_B)         // 1256
#define TOTB (HISTB + SCANB + 1)        // +1 new-logit/init writer CTA
#define FLAG_THR (-100.0f)
#define SGRP 8                          // samples per k_boot CTA
#define NGRP ((NS + 1 + SGRP - 1) / SGRP)   // 13

// scratch (no allocations allowed)
__device__ float g_logits[BB * KC];            // UB for unflagged live, exact for flagged/new
__device__ float g_boot[NS * BB * DD];         // [n][b*DD+d]  (coalesced both sides)
__device__ int   g_cnt[NS * BB * 32];          // per-sample new-particle counts
__device__ unsigned g_MliveU[BB];              // encoded max flagged live logit (0 = none; reset by k_final)
__device__ int   g_flag[BB];                   // converged flags (init by k_scan writer CTA)
__device__ int   g_tick = 0;                   // k_final ticket (reset by last CTA)

__device__ __forceinline__ unsigned fenc(float f) {
    unsigned u = __float_as_uint(f);
    return (u & 0x80000000u) ? ~u : (u | 0x80000000u);
}
__device__ __forceinline__ float fdec(unsigned u) {
    return (u & 0x80000000u) ? __uint_as_float(u & 0x7FFFFFFFu) : __uint_as_float(~u);
}

__device__ __forceinline__ float dsq(float4 a, float4 c) {
    float d0 = a.x - c.x, d1 = a.y - c.y, d2 = a.z - c.z, d3 = a.w - c.w;
    return d0 * d0 + d1 * d1 + d2 * d2 + d3 * d3;
}

__device__ __forceinline__ float blockMax256(float v, float* red) {
#pragma unroll
    for (int o = 16; o; o >>= 1) v = fmaxf(v, __shfl_xor_sync(0xffffffffu, v, o));
    int wid = threadIdx.x >> 5;
    if ((threadIdx.x & 31) == 0) red[wid] = v;
    __syncthreads();
    if (threadIdx.x < 32) {
        float x = (threadIdx.x < 8) ? red[threadIdx.x] : -INFINITY;
#pragma unroll
        for (int o = 4; o; o >>= 1) x = fmaxf(x, __shfl_xor_sync(0xffffffffu, x, o));
        if (threadIdx.x == 0) red[0] = x;
    }
    __syncthreads();
    v = red[0];
    __syncthreads();
    return v;
}

__device__ __forceinline__ float blockSum256(float v, float* red) {
#pragma unroll
    for (int o = 16; o; o >>= 1) v += __shfl_xor_sync(0xffffffffu, v, o);
    int wid = threadIdx.x >> 5;
    if ((threadIdx.x & 31) == 0) red[wid] = v;
    __syncthreads();
    if (threadIdx.x < 32) {
        float x = (threadIdx.x < 8) ? red[threadIdx.x] : 0.f;
#pragma unroll
        for (int o = 4; o; o >>= 1) x += __shfl_xor_sync(0xffffffffu, x, o);
        if (threadIdx.x == 0) red[0] = x;
    }
    __syncthreads();
    v = red[0];
    __syncthreads();
    return v;
}

// ---------- kernel 1: idx histogram + partial scan + inline exact resolve ----------
__global__ void k_scan(const float* __restrict__ xt,
                       const float* __restrict__ live_x0,
                       const float* __restrict__ live_ll,
                       const float* __restrict__ ll,
                       const float* __restrict__ tsp,
                       const int* __restrict__ bidx) {
    __shared__ int cnt32[32];
    __shared__ int fl_rows[ROWS_PER_CTA];
    __shared__ int fl_n;
    int bid = blockIdx.x, t = threadIdx.x;

    if (bid < HISTB) {
        // histogram of idx over the new-particle range [NL, KC)
        int n = bid >> 3, b = bid & 7;
        if (t < 32) cnt32[t] = 0;
        __syncthreads();
        const uint4* src = (const uint4*)(bidx + ((size_t)n * BB + b) * KC);
        for (int i = t; i < KC / 4; i += 256) {
            uint4 v = src[i];
            int s0 = (int)v.x - NL, s1 = (int)v.y - NL;
            int s2 = (int)v.z - NL, s3 = (int)v.w - NL;
            if (s0 >= 0) atomicAdd(&cnt32[s0], 1);
            if (s1 >= 0) atomicAdd(&cnt32[s1], 1);
            if (s2 >= 0) atomicAdd(&cnt32[s2], 1);
            if (s3 >= 0) atomicAdd(&cnt32[s3], 1);
        }
        __syncthreads();
        if (t < 32) g_cnt[((size_t)n * BB + b) * 32 + t] = cnt32[t];
        return;
    }
    if (bid == HISTB + SCANB) {
        // new-particle logits: exactly ll (gaussian correction cancels); init flags
        int b = t >> 5, j = t & 31;
        g_logits[(size_t)b * KC + NL + j] = ll[b * KN + j];
        if (t < BB) g_flag[t] = 1;
        return;
    }

    // partial scan: first 64 dims of each live row -> upper bound on its logit.
    int s = bid - HISTB;
    int b = s / SCAN_PER_B;
    int r0 = (s - b * SCAN_PER_B) * ROWS_PER_CTA;
    int w = t >> 5, lane = t & 31;
    int half = lane >> 4, sl = lane & 15;

    if (t == 0) fl_n = 0;
    __syncthreads();

    float ts = *tsp;
    float inv2 = 0.5f / (ts * ts), lg = logf(ts);
    const float4* xtr = (const float4*)(xt + (size_t)b * DD);
    float4 c = xtr[sl];  // first 64 floats of xt

    int rbase = r0 + w * 8 + half;  // rows rbase, rbase+2, rbase+4, rbase+6
    const float4* lx = (const float4*)(live_x0 + (size_t)b * NL * DD);

    int row0 = rbase, row1 = rbase + 2, row2 = rbase + 4, row3 = rbase + 6;
    bool v0 = row0 < NL, v1 = row1 < NL, v2 = row2 < NL, v3 = row3 < NL;
    float4 a0 = v0 ? lx[(size_t)row0 * (DD / 4) + sl] : c;
    float4 a1 = v1 ? lx[(size_t)row1 * (DD / 4) + sl] : c;
    float4 a2 = v2 ? lx[(size_t)row2 * (DD / 4) + sl] : c;
    float4 a3 = v3 ? lx[(size_t)row3 * (DD / 4) + sl] : c;
    float q0 = dsq(a0, c), q1 = dsq(a1, c), q2 = dsq(a2, c), q3 = dsq(a3, c);
#pragma unroll
    for (int o = 8; o; o >>= 1) {  // reduce within 16-lane half-warp
        q0 += __shfl_xor_sync(0xffffffffu, q0, o);
        q1 += __shfl_xor_sync(0xffffffffu, q1, o);
        q2 += __shfl_xor_sync(0xffffffffu, q2, o);
        q3 += __shfl_xor_sync(0xffffffffu, q3, o);
    }
    if (sl == 0) {
        const float* lr = live_ll + (size_t)b * NL;
        float* Lb = g_logits + (size_t)b * KC;
        float qs[4] = {q0, q1, q2, q3};
#pragma unroll
        for (int j = 0; j < 4; j++) {
            int row = rbase + 2 * j;
            if (row < NL) {
                float ub = lr[row] - qs[j] * inv2 - lg;   // upper bound (partial distance >= 0)
                Lb[row] = ub;
                if (ub > FLAG_THR) {
                    int pos = atomicAdd(&fl_n, 1);
                    fl_rows[pos] = row;   // <= 64 rows per CTA by construction
                }
            }
        }
    }
    __syncthreads();

    // inline exact resolve for flagged rows (rare): full 256-dim distance, warp per row
    int nf = fl_n;
    if (nf > 0) {
        float4 c0 = xtr[lane], c1 = xtr[lane + 32];
        for (int i = w; i < nf; i += 8) {
            int row = fl_rows[i];
            const float4* r = (const float4*)(live_x0 + ((size_t)b * NL + row) * DD);
            float4 e0 = r[lane], e1 = r[lane + 32];
            float sfull = dsq(e0, c0) + dsq(e1, c1);
#pragma unroll
            for (int o = 16; o; o >>= 1) sfull += __shfl_xor_sync(0xffffffffu, sfull, o);
            if (lane == 0) {
                float l = live_ll[(size_t)b * NL + row] - sfull * inv2 - lg;
                g_logits[(size_t)b * KC + row] = l;   // overwrite UB with exact
                atomicMax(&g_MliveU[b], fenc(l));
            }
        }
    }
}

// ---------- kernel 2: bootstrap + score, 8 samples per CTA with smem x0 slab ----------
// grid = (NGRP, BB); CTA g handles samples n = g*8 .. g*8+7 (n == NS is the score).
__global__ void k_boot(const float* __restrict__ xt,
                       const float* __restrict__ live_x0,
                       const float* __restrict__ x0,
                       const float* __restrict__ ll,
                       const int* __restrict__ bidx,
                       const float* __restrict__ tsp,
                       float* __restrict__ out) {
    __shared__ float xs[KN * DD];        // 32 KB: x0[b] slab
    __shared__ float wsm[KN][SGRP];      // weights [row j][sample s]
    __shared__ float zvec[SGRP];
    __shared__ int   fastv[SGRP];        // 0=slow, 1=fast, 2=invalid
    __shared__ float red[8];
    int g = blockIdx.x, b = blockIdx.y, t = threadIdx.x;
    int w = t >> 5, lane = t & 31;
    int n0 = g * SGRP;
    float ts = *tsp;

    // load x0 slab (coalesced float4)
    {
        const float4* src = (const float4*)(x0 + (size_t)b * KN * DD);
        float4* dst = (float4*)xs;
#pragma unroll
        for (int i = 0; i < (KN * DD / 4) / 256; i++) dst[t + i * 256] = src[t + i * 256];
    }

    // warp w computes weights for sample n0+w (identical numerics to per-CTA version)
    {
        int n = n0 + w;
        if (n <= NS) {
            int c = (n == NS) ? 1 : g_cnt[((size_t)n * BB + b) * 32 + lane];
            float lv = ll[b * KN + lane];
            float m = (c > 0) ? lv : -INFINITY;
#pragma unroll
            for (int o = 16; o; o >>= 1) m = fmaxf(m, __shfl_xor_sync(0xffffffffu, m, o));
            float wt = (c > 0) ? (float)c * expf(lv - m) : 0.f;
            float z = wt;
#pragma unroll
            for (int o = 16; o; o >>= 1) z += __shfl_xor_sync(0xffffffffu, z, o);
            wsm[lane][w] = wt;
            if (lane == 0) {
                zvec[w] = z;
                unsigned mu = g_MliveU[b];
                float Mlive = mu ? fdec(mu) : -INFINITY;
                Mlive = fmaxf(Mlive, FLAG_THR);
                fastv[w] = ((m > -INFINITY) && (Mlive <= m - 90.f)) ? 1 : 0;
            }
        } else if (lane == 0) {
            fastv[w] = 2;
        }
    }
    __syncthreads();

    float xtv = xt[(size_t)b * DD + t];
    float acc[SGRP];
#pragma unroll
    for (int s = 0; s < SGRP; s++) acc[s] = 0.f;

    // fused weighted sum: row j once from smem, 8 FMA into 8 accumulators
#pragma unroll 4
    for (int j = 0; j < KN; j++) {
        float xj = xs[j * DD + t];
        const float4* wp = (const float4*)&wsm[j][0];
        float4 w0 = wp[0], w1 = wp[1];
        acc[0] = fmaf(w0.x, xj, acc[0]); acc[1] = fmaf(w0.y, xj, acc[1]);
        acc[2] = fmaf(w0.z, xj, acc[2]); acc[3] = fmaf(w0.w, xj, acc[3]);
        acc[4] = fmaf(w1.x, xj, acc[4]); acc[5] = fmaf(w1.y, xj, acc[5]);
        acc[6] = fmaf(w1.z, xj, acc[6]); acc[7] = fmaf(w1.w, xj, acc[7]);
    }

#pragma unroll
    for (int s = 0; s < SGRP; s++) {
        int n = n0 + s;
        if (fastv[s] == 1) {
            float val = acc[s] / (zvec[s] * ts) - xtv / ts;
            if (n == NS) out[(size_t)b * DD + t] = val;
            else         g_boot[(size_t)n * (BB * DD) + b * DD + t] = val;
        }
    }

    // exact slow path for any non-fast sample (never taken with this data)
    for (int s = 0; s < SGRP; s++) {
        if (fastv[s] != 0) continue;
        int n = n0 + s;
        bool is_score = (n == NS);
        const int* idx = bidx + ((size_t)n * BB + b) * KC;
        const float* L = g_logits + (size_t)b * KC;
        float mm = -INFINITY;
        if (is_score) { for (int k = t; k < KC; k += 256) mm = fmaxf(mm, L[k]); }
        else          { for (int i = t; i < KC; i += 256) mm = fmaxf(mm, L[idx[i]]); }
        mm = blockMax256(mm, red);
        float zz = 0.f;
        if (is_score) { for (int k = t; k < KC; k += 256) zz += expf(L[k] - mm); }
        else          { for (int i = t; i < KC; i += 256) zz += expf(L[idx[i]] - mm); }
        float z = blockSum256(zz, red);
        float a = 0.f;
        for (int i = 0; i < KC; i++) {
            int k = is_score ? i : idx[i];
            float wv = expf(L[k] - mm);
            if (wv != 0.f) {
                const float* r = (k < NL) ? live_x0 + ((size_t)b * NL + k) * DD
                                          : x0 + ((size_t)b * KN + (k - NL)) * DD;
                a = fmaf(wv, r[t], a);
            }
        }
        float val = a / (z * ts) - xtv / ts;
        if (is_score) out[(size_t)b * DD + t] = val;
        else          g_boot[(size_t)n * (BB * DD) + b * DD + t] = val;
    }
}

// ---------- kernel 3: std (ddof=1) + flags, 32 CTAs (4 per b) ----------
__global__ void k_final(const float* __restrict__ tsp, float* __restrict__ out, int out_size) {
    __shared__ float sred[4][64];
    __shared__ int tick;
    int cta = blockIdx.x;
    int b = cta >> 2, dg = cta & 3;
    int dj = threadIdx.x & 63, ng = threadIdx.x >> 6;
    int d = dg * 64 + dj;
    const float* p = g_boot + (size_t)b * DD + d + (size_t)(ng * 25) * (BB * DD);

    float x[25];
#pragma unroll
    for (int i = 0; i < 25; i++) x[i] = p[(size_t)i * (BB * DD)];
    float s = 0.f;
#pragma unroll
    for (int i = 0; i < 25; i++) s += x[i];
    sred[ng][dj] = s;
    __syncthreads();
    float mean = (sred[0][dj] + sred[1][dj] + sred[2][dj] + sred[3][dj]) * (1.f / NS);
    __syncthreads();
    float q = 0.f;
#pragma unroll
    for (int i = 0; i < 25; i++) { float dv = x[i] - mean; q = fmaf(dv, dv, q); }
    sred[ng][dj] = q;
    __syncthreads();

    int ok = 1;
    if (ng == 0) {
        float qt = sred[0][dj] + sred[1][dj] + sred[2][dj] + sred[3][dj];
        float sigma = sqrtf(qt * (1.f / (NS - 1)));
        ok = sigma < 0.1f * (*tsp);
    }
    int all = __syncthreads_and(ok);
    if (threadIdx.x == 0 && !all) atomicAnd(&g_flag[b], 0);
    __threadfence();
    __syncthreads();
    if (threadIdx.x == 0) tick = atomicAdd(&g_tick, 1);
    __syncthreads();
    if (tick == 31) {  // last CTA: emit flags + reset replay state
        if (threadIdx.x < BB) {
            if (out_size >= BB * DD + BB)
                out[BB * DD + threadIdx.x] = g_flag[threadIdx.x] ? 1.f : 0.f;
            g_MliveU[threadIdx.x] = 0u;
        }
        if (threadIdx.x == 0) g_tick = 0;
    }
}

extern "C" void kernel_launch(void* const* d_in, const int* in_sizes, int n_in,
                              void* d_out, int out_size) {
    const float* xt      = (const float*)d_in[0];
    const float* live_x0 = (const float*)d_in[1];
    const float* live_ll = (const float*)d_in[2];
    const float* x0      = (const float*)d_in[3];
    const float* ll      = (const float*)d_in[4];
    const float* tsp     = (const float*)d_in[5];
    const int*   bidx    = (const int*)d_in[6];
    float* out = (float*)d_out;

    k_scan<<<TOTB, 256>>>(xt, live_x0, live_ll, ll, tsp, bidx);

    dim3 g2(NGRP, BB);
    k_boot<<<g2, 256>>>(xt, live_x0, x0, ll, bidx, tsp, out);

    k_final<<<32, 256>>>(tsp, out, out_size);
}

// round 16
// speedup vs baseline: 2.1640x; 1.0332x over previous
#include <cuda_runtime.h>
#include <math.h>

#define BB 8
#define DD 256
#define NL 10000
#define KN 32
#define KC 10032
#define NS 100

#define HISTB (NS * BB)                 // 800 histogram CTAs
#define ROWS_PER_CTA 64
#define SCAN_PER_B ((NL + ROWS_PER_CTA - 1) / ROWS_PER_CTA)   // 157
#define SCANB (BB * SCAN_PER_B)         // 1256
#define TOTB (HISTB + SCANB + 1)        // +1 new-logit writer CTA
#define FLAG_THR (-100.0f)
#define SGRP 8                          // samples per k_boot CTA
#define NGRP ((NS + 1 + SGRP - 1) / SGRP)   // 13

// scratch (no allocations allowed)
__device__ float g_logits[BB * KC];            // UB for unflagged live, exact for flagged/new
__device__ float g_boot[NS * BB * DD];         // [n][b*DD+d]  (coalesced both sides)
__device__ int   g_cnt[NS * BB * 32];          // per-sample new-particle counts
__device__ unsigned g_MliveU[BB];              // encoded max flagged live logit (0 = none; reset by reducer)
__device__ int   g_bcnt[BB];                   // per-b boot-CTA tickets (reset by reducer)

__device__ __forceinline__ unsigned fenc(float f) {
    unsigned u = __float_as_uint(f);
    return (u & 0x80000000u) ? ~u : (u | 0x80000000u);
}
__device__ __forceinline__ float fdec(unsigned u) {
    return (u & 0x80000000u) ? __uint_as_float(u & 0x7FFFFFFFu) : __uint_as_float(~u);
}

__device__ __forceinline__ float dsq(float4 a, float4 c) {
    float d0 = a.x - c.x, d1 = a.y - c.y, d2 = a.z - c.z, d3 = a.w - c.w;
    return d0 * d0 + d1 * d1 + d2 * d2 + d3 * d3;
}

__device__ __forceinline__ float blockMax256(float v, float* red) {
#pragma unroll
    for (int o = 16; o; o >>= 1) v = fmaxf(v, __shfl_xor_sync(0xffffffffu, v, o));
    int wid = threadIdx.x >> 5;
    if ((threadIdx.x & 31) == 0) red[wid] = v;
    __syncthreads();
    if (threadIdx.x < 32) {
        float x = (threadIdx.x < 8) ? red[threadIdx.x] : -INFINITY;
#pragma unroll
        for (int o = 4; o; o >>= 1) x = fmaxf(x, __shfl_xor_sync(0xffffffffu, x, o));
        if (threadIdx.x == 0) red[0] = x;
    }
    __syncthreads();
    v = red[0];
    __syncthreads();
    return v;
}

__device__ __forceinline__ float blockSum256(float v, float* red) {
#pragma unroll
    for (int o = 16; o; o >>= 1) v += __shfl_xor_sync(0xffffffffu, v, o);
    int wid = threadIdx.x >> 5;
    if ((threadIdx.x & 31) == 0) red[wid] = v;
    __syncthreads();
    if (threadIdx.x < 32) {
        float x = (threadIdx.x < 8) ? red[threadIdx.x] : 0.f;
#pragma unroll
        for (int o = 4; o; o >>= 1) x += __shfl_xor_sync(0xffffffffu, x, o);
        if (threadIdx.x == 0) red[0] = x;
    }
    __syncthreads();
    v = red[0];
    __syncthreads();
    return v;
}

// ---------- kernel 1: idx histogram + partial scan + inline exact resolve ----------
__global__ void k_scan(const float* __restrict__ xt,
                       const float* __restrict__ live_x0,
                       const float* __restrict__ live_ll,
                       const float* __restrict__ ll,
                       const float* __restrict__ tsp,
                       const int* __restrict__ bidx) {
    __shared__ int cnt32[32];
    __shared__ int fl_rows[ROWS_PER_CTA];
    __shared__ int fl_n;
    int bid = blockIdx.x, t = threadIdx.x;

    if (bid < HISTB) {
        // histogram of idx over the new-particle range [NL, KC)
        int n = bid >> 3, b = bid & 7;
        if (t < 32) cnt32[t] = 0;
        __syncthreads();
        const uint4* src = (const uint4*)(bidx + ((size_t)n * BB + b) * KC);
        for (int i = t; i < KC / 4; i += 256) {
            uint4 v = src[i];
            int s0 = (int)v.x - NL, s1 = (int)v.y - NL;
            int s2 = (int)v.z - NL, s3 = (int)v.w - NL;
            if (s0 >= 0) atomicAdd(&cnt32[s0], 1);
            if (s1 >= 0) atomicAdd(&cnt32[s1], 1);
            if (s2 >= 0) atomicAdd(&cnt32[s2], 1);
            if (s3 >= 0) atomicAdd(&cnt32[s3], 1);
        }
        __syncthreads();
        if (t < 32) g_cnt[((size_t)n * BB + b) * 32 + t] = cnt32[t];
        return;
    }
    if (bid == HISTB + SCANB) {
        // new-particle logits: exactly ll (gaussian correction cancels)
        int b = t >> 5, j = t & 31;
        g_logits[(size_t)b * KC + NL + j] = ll[b * KN + j];
        return;
    }

    // partial scan: first 64 dims of each live row -> upper bound on its logit.
    int s = bid - HISTB;
    int b = s / SCAN_PER_B;
    int r0 = (s - b * SCAN_PER_B) * ROWS_PER_CTA;
    int w = t >> 5, lane = t & 31;
    int half = lane >> 4, sl = lane & 15;

    if (t == 0) fl_n = 0;
    __syncthreads();

    float ts = *tsp;
    float inv2 = 0.5f / (ts * ts), lg = logf(ts);
    const float4* xtr = (const float4*)(xt + (size_t)b * DD);
    float4 c = xtr[sl];  // first 64 floats of xt

    int rbase = r0 + w * 8 + half;  // rows rbase, rbase+2, rbase+4, rbase+6
    const float4* lx = (const float4*)(live_x0 + (size_t)b * NL * DD);

    int row0 = rbase, row1 = rbase + 2, row2 = rbase + 4, row3 = rbase + 6;
    bool v0 = row0 < NL, v1 = row1 < NL, v2 = row2 < NL, v3 = row3 < NL;
    float4 a0 = v0 ? lx[(size_t)row0 * (DD / 4) + sl] : c;
    float4 a1 = v1 ? lx[(size_t)row1 * (DD / 4) + sl] : c;
    float4 a2 = v2 ? lx[(size_t)row2 * (DD / 4) + sl] : c;
    float4 a3 = v3 ? lx[(size_t)row3 * (DD / 4) + sl] : c;
    float q0 = dsq(a0, c), q1 = dsq(a1, c), q2 = dsq(a2, c), q3 = dsq(a3, c);
#pragma unroll
    for (int o = 8; o; o >>= 1) {  // reduce within 16-lane half-warp
        q0 += __shfl_xor_sync(0xffffffffu, q0, o);
        q1 += __shfl_xor_sync(0xffffffffu, q1, o);
        q2 += __shfl_xor_sync(0xffffffffu, q2, o);
        q3 += __shfl_xor_sync(0xffffffffu, q3, o);
    }
    if (sl == 0) {
        const float* lr = live_ll + (size_t)b * NL;
        float* Lb = g_logits + (size_t)b * KC;
        float qs[4] = {q0, q1, q2, q3};
#pragma unroll
        for (int j = 0; j < 4; j++) {
            int row = rbase + 2 * j;
            if (row < NL) {
                float ub = lr[row] - qs[j] * inv2 - lg;   // upper bound (partial distance >= 0)
                Lb[row] = ub;
                if (ub > FLAG_THR) {
                    int pos = atomicAdd(&fl_n, 1);
                    fl_rows[pos] = row;   // <= 64 rows per CTA by construction
                }
            }
        }
    }
    __syncthreads();

    // inline exact resolve for flagged rows (rare): full 256-dim distance, warp per row
    int nf = fl_n;
    if (nf > 0) {
        float4 c0 = xtr[lane], c1 = xtr[lane + 32];
        for (int i = w; i < nf; i += 8) {
            int row = fl_rows[i];
            const float4* r = (const float4*)(live_x0 + ((size_t)b * NL + row) * DD);
            float4 e0 = r[lane], e1 = r[lane + 32];
            float sfull = dsq(e0, c0) + dsq(e1, c1);
#pragma unroll
            for (int o = 16; o; o >>= 1) sfull += __shfl_xor_sync(0xffffffffu, sfull, o);
            if (lane == 0) {
                float l = live_ll[(size_t)b * NL + row] - sfull * inv2 - lg;
                g_logits[(size_t)b * KC + row] = l;   // overwrite UB with exact
                atomicMax(&g_MliveU[b], fenc(l));
            }
        }
    }
}

// ---------- kernel 2: bootstrap + score + fused per-b std/flag (grid = [NGRP, BB]) ----------
// CTA g handles samples n = g*8 .. g*8+7 (n == NS is the score). Last CTA per b
// (ticket == NGRP-1) reduces that b's std + writes the converged flag + resets state.
__global__ void k_boot(const float* __restrict__ xt,
                       const float* __restrict__ live_x0,
                       const float* __restrict__ x0,
                       const float* __restrict__ ll,
                       const int* __restrict__ bidx,
                       const float* __restrict__ tsp,
                       float* __restrict__ out, int out_size) {
    __shared__ float xs[KN * DD];        // 32 KB: x0[b] slab
    __shared__ float wsm[KN][SGRP];      // weights [row j][sample s]
    __shared__ float zvec[SGRP];
    __shared__ int   fastv[SGRP];        // 0=slow, 1=fast, 2=invalid
    __shared__ float red[8];
    __shared__ int   sh_tick;
    int g = blockIdx.x, b = blockIdx.y, t = threadIdx.x;
    int w = t >> 5, lane = t & 31;
    int n0 = g * SGRP;
    float ts = *tsp;

    // load x0 slab (coalesced float4)
    {
        const float4* src = (const float4*)(x0 + (size_t)b * KN * DD);
        float4* dst = (float4*)xs;
#pragma unroll
        for (int i = 0; i < (KN * DD / 4) / 256; i++) dst[t + i * 256] = src[t + i * 256];
    }

    // warp w computes weights for sample n0+w
    {
        int n = n0 + w;
        if (n <= NS) {
            int c = (n == NS) ? 1 : g_cnt[((size_t)n * BB + b) * 32 + lane];
            float lv = ll[b * KN + lane];
            float m = (c > 0) ? lv : -INFINITY;
#pragma unroll
            for (int o = 16; o; o >>= 1) m = fmaxf(m, __shfl_xor_sync(0xffffffffu, m, o));
            float wt = (c > 0) ? (float)c * expf(lv - m) : 0.f;
            float z = wt;
#pragma unroll
            for (int o = 16; o; o >>= 1) z += __shfl_xor_sync(0xffffffffu, z, o);
            wsm[lane][w] = wt;
            if (lane == 0) {
                zvec[w] = z;
                unsigned mu = g_MliveU[b];
                float Mlive = mu ? fdec(mu) : -INFINITY;
                Mlive = fmaxf(Mlive, FLAG_THR);
                fastv[w] = ((m > -INFINITY) && (Mlive <= m - 90.f)) ? 1 : 0;
            }
        } else if (lane == 0) {
            fastv[w] = 2;
        }
    }
    __syncthreads();

    float xtv = xt[(size_t)b * DD + t];
    float acc[SGRP];
#pragma unroll
    for (int s = 0; s < SGRP; s++) acc[s] = 0.f;

    // fused weighted sum: row j once from smem, 8 FMA into 8 accumulators
#pragma unroll 4
    for (int j = 0; j < KN; j++) {
        float xj = xs[j * DD + t];
        const float4* wp = (const float4*)&wsm[j][0];
        float4 w0 = wp[0], w1 = wp[1];
        acc[0] = fmaf(w0.x, xj, acc[0]); acc[1] = fmaf(w0.y, xj, acc[1]);
        acc[2] = fmaf(w0.z, xj, acc[2]); acc[3] = fmaf(w0.w, xj, acc[3]);
        acc[4] = fmaf(w1.x, xj, acc[4]); acc[5] = fmaf(w1.y, xj, acc[5]);
        acc[6] = fmaf(w1.z, xj, acc[6]); acc[7] = fmaf(w1.w, xj, acc[7]);
    }

#pragma unroll
    for (int s = 0; s < SGRP; s++) {
        int n = n0 + s;
        if (fastv[s] == 1) {
            float val = acc[s] / (zvec[s] * ts) - xtv / ts;
            if (n == NS) out[(size_t)b * DD + t] = val;
            else         g_boot[(size_t)n * (BB * DD) + b * DD + t] = val;
        }
    }

    // exact slow path for any non-fast sample (never taken with this data)
    for (int s = 0; s < SGRP; s++) {
        if (fastv[s] != 0) continue;
        int n = n0 + s;
        bool is_score = (n == NS);
        const int* idx = bidx + ((size_t)n * BB + b) * KC;
        const float* L = g_logits + (size_t)b * KC;
        float mm = -INFINITY;
        if (is_score) { for (int k = t; k < KC; k += 256) mm = fmaxf(mm, L[k]); }
        else          { for (int i = t; i < KC; i += 256) mm = fmaxf(mm, L[idx[i]]); }
        mm = blockMax256(mm, red);
        float zz = 0.f;
        if (is_score) { for (int k = t; k < KC; k += 256) zz += expf(L[k] - mm); }
        else          { for (int i = t; i < KC; i += 256) zz += expf(L[idx[i]] - mm); }
        float z = blockSum256(zz, red);
        float a = 0.f;
        for (int i = 0; i < KC; i++) {
            int k = is_score ? i : idx[i];
            float wv = expf(L[k] - mm);
            if (wv != 0.f) {
                const float* r = (k < NL) ? live_x0 + ((size_t)b * NL + k) * DD
                                          : x0 + ((size_t)b * KN + (k - NL)) * DD;
                a = fmaf(wv, r[t], a);
            }
        }
        float val = a / (z * ts) - xtv / ts;
        if (is_score) out[(size_t)b * DD + t] = val;
        else          g_boot[(size_t)n * (BB * DD) + b * DD + t] = val;
    }

    // ---- per-b ticket: last CTA reduces this b's std + emits flag + resets state ----
    __threadfence();
    __syncthreads();
    if (t == 0) sh_tick = atomicAdd(&g_bcnt[b], 1);
    __syncthreads();
    if (sh_tick == NGRP - 1) {
        const float* p = g_boot + (size_t)b * DD + t;
        float x[NS];
#pragma unroll
        for (int i = 0; i < NS; i++) x[i] = p[(size_t)i * (BB * DD)];
        float sm = 0.f;
#pragma unroll
        for (int i = 0; i < NS; i++) sm += x[i];
        float mean = sm * (1.f / NS);
        float q = 0.f;
#pragma unroll
        for (int i = 0; i < NS; i++) { float dv = x[i] - mean; q = fmaf(dv, dv, q); }
        float sigma = sqrtf(q * (1.f / (NS - 1)));
        int ok = sigma < 0.1f * ts;
        int all = __syncthreads_and(ok);
        if (t == 0) {
            if (out_size >= BB * DD + BB) out[BB * DD + b] = all ? 1.f : 0.f;
            g_bcnt[b] = 0;      // reset for next graph replay
            g_MliveU[b] = 0u;
        }
    }
}

extern "C" void kernel_launch(void* const* d_in, const int* in_sizes, int n_in,
                              void* d_out, int out_size) {
    const float* xt      = (const float*)d_in[0];
    const float* live_x0 = (const float*)d_in[1];
    const float* live_ll = (const float*)d_in[2];
    const float* x0      = (const float*)d_in[3];
    const float* ll      = (const float*)d_in[4];
    const float* tsp     = (const float*)d_in[5];
    const int*   bidx    = (const int*)d_in[6];
    float* out = (float*)d_out;

    k_scan<<<TOTB, 256>>>(xt, live_x0, live_ll, ll, tsp, bidx);

    dim3 g2(NGRP, BB);
    k_boot<<<g2, 256>>>(xt, live_x0, x0, ll, bidx, tsp, out, out_size);
}